// round 16
// baseline (speedup 1.0000x reference)
#include <cuda_runtime.h>
#include <cstdint>

#define N_MAX 100000
#define D 64

__device__ __align__(16) int   g_deg [N_MAX];
__device__ __align__(16) float g_dinv[N_MAX];
__device__ __align__(16) float g_hs  [N_MAX * D];
__device__ __align__(16) float g_agg [N_MAX * D];

// ---------------- degree / norm ----------------

__global__ void k_init_deg(int n) {
    int i = blockIdx.x * blockDim.x + threadIdx.x;
    if (i < n) g_deg[i] = 1;                 // self-loop
}

__global__ void k_count(const int* __restrict__ ei, int E) {
    int e = blockIdx.x * blockDim.x + threadIdx.x;
    if (e < E) atomicAdd(&g_deg[ei[E + e]], 1);
}

__global__ void k_dinv(int n) {
    int i = blockIdx.x * blockDim.x + threadIdx.x;
    if (i < n) g_dinv[i] = rsqrtf((float)g_deg[i]);
}

// ---------------- fused GEMM, 2x4 register blocking, 512 threads ----------
// mode 0: in = X; mode 1: in = prelu(g_agg * dinv + b, a) (fused L1 epilogue)
// output: hs = (in @ W) * dinv ; agg = hs (self-loop init)
//
// Block tile 64 nodes x 64 cols, 512 threads. Thread (tn = t>>4, tj = t&15)
// computes nodes {2tn, 2tn+1} x cols {tj+16*dc}: 8 accumulators -> <=64 regs,
// 2 blocks/SM = 32 warps (8/SMSP) for LDS-latency hiding.
// W rows tj+16dc, 68-word stride: bank group tj+4dc+k4 mod 8 is bijective per
// 8-lane phase -> conflict-free LDS.128. xs rows padded to 17 float4.

__global__ void __launch_bounds__(512, 2)
k_gemm(const float* __restrict__ X, const float* __restrict__ W,
       const float* __restrict__ bp, const float* __restrict__ ap,
       int n, int mode)
{
    __shared__ __align__(16) float  Wt[D][68];    // Wt[j][k] = W[k*64+j]
    __shared__ __align__(16) float4 xs[64][17];   // padded row: 68 words
    int t = threadIdx.x;

    // stage W transposed (coalesced reads)
    #pragma unroll
    for (int r = 0; r < 8; r++) {
        int i = t + 512 * r;
        Wt[i & 63][i >> 6] = W[i];
    }

    int base = blockIdx.x * 64;

    // stage input tile (coalesced float4), fusing layer-1 epilogue in mode 1
    #pragma unroll
    for (int r = 0; r < 2; r++) {
        int i = t + 512 * r;
        int node = base + (i >> 4);
        int k4 = i & 15;
        float4 v = make_float4(0.f, 0.f, 0.f, 0.f);
        if (node < n) {
            if (mode == 0) {
                v = ((const float4*)X)[(size_t)node * 16 + k4];
            } else {
                v = ((const float4*)g_agg)[(size_t)node * 16 + k4];
                float dv = g_dinv[node];
                float4 bb = ((const float4*)bp)[k4];
                float4 aa = ((const float4*)ap)[k4];
                v.x = v.x * dv + bb.x; v.x = (v.x >= 0.f) ? v.x : aa.x * v.x;
                v.y = v.y * dv + bb.y; v.y = (v.y >= 0.f) ? v.y : aa.y * v.y;
                v.z = v.z * dv + bb.z; v.z = (v.z >= 0.f) ? v.z : aa.z * v.z;
                v.w = v.w * dv + bb.w; v.w = (v.w >= 0.f) ? v.w : aa.w * v.w;
            }
        }
        xs[i >> 4][k4] = v;
    }
    __syncthreads();

    int tj = t & 15, tn = t >> 4;
    int n0 = 2 * tn;

    // acc{q}.{x,y,z,w} = node n0+q, columns tj+{0,16,32,48}
    float4 acc0 = make_float4(0.f,0.f,0.f,0.f);
    float4 acc1 = acc0;

    #pragma unroll
    for (int k4 = 0; k4 < 16; k4++) {
        float4 x0 = xs[n0 + 0][k4];
        float4 x1 = xs[n0 + 1][k4];
        float4 w0 = *(const float4*)&Wt[tj +  0][4 * k4];
        float4 w1 = *(const float4*)&Wt[tj + 16][4 * k4];
        float4 w2 = *(const float4*)&Wt[tj + 32][4 * k4];
        float4 w3 = *(const float4*)&Wt[tj + 48][4 * k4];

        acc0.x = fmaf(x0.x, w0.x, acc0.x); acc0.x = fmaf(x0.y, w0.y, acc0.x);
        acc0.x = fmaf(x0.z, w0.z, acc0.x); acc0.x = fmaf(x0.w, w0.w, acc0.x);
        acc0.y = fmaf(x0.x, w1.x, acc0.y); acc0.y = fmaf(x0.y, w1.y, acc0.y);
        acc0.y = fmaf(x0.z, w1.z, acc0.y); acc0.y = fmaf(x0.w, w1.w, acc0.y);
        acc0.z = fmaf(x0.x, w2.x, acc0.z); acc0.z = fmaf(x0.y, w2.y, acc0.z);
        acc0.z = fmaf(x0.z, w2.z, acc0.z); acc0.z = fmaf(x0.w, w2.w, acc0.z);
        acc0.w = fmaf(x0.x, w3.x, acc0.w); acc0.w = fmaf(x0.y, w3.y, acc0.w);
        acc0.w = fmaf(x0.z, w3.z, acc0.w); acc0.w = fmaf(x0.w, w3.w, acc0.w);

        acc1.x = fmaf(x1.x, w0.x, acc1.x); acc1.x = fmaf(x1.y, w0.y, acc1.x);
        acc1.x = fmaf(x1.z, w0.z, acc1.x); acc1.x = fmaf(x1.w, w0.w, acc1.x);
        acc1.y = fmaf(x1.x, w1.x, acc1.y); acc1.y = fmaf(x1.y, w1.y, acc1.y);
        acc1.y = fmaf(x1.z, w1.z, acc1.y); acc1.y = fmaf(x1.w, w1.w, acc1.y);
        acc1.z = fmaf(x1.x, w2.x, acc1.z); acc1.z = fmaf(x1.y, w2.y, acc1.z);
        acc1.z = fmaf(x1.z, w2.z, acc1.z); acc1.z = fmaf(x1.w, w2.w, acc1.z);
        acc1.w = fmaf(x1.x, w3.x, acc1.w); acc1.w = fmaf(x1.y, w3.y, acc1.w);
        acc1.w = fmaf(x1.z, w3.z, acc1.w); acc1.w = fmaf(x1.w, w3.w, acc1.w);
    }

    float4 accs[2] = {acc0, acc1};
    #pragma unroll
    for (int q = 0; q < 2; q++) {
        int node = base + n0 + q;
        if (node < n) {
            float dv = g_dinv[node];
            size_t o = (size_t)node * D + tj;
            float v0 = accs[q].x * dv;
            float v1 = accs[q].y * dv;
            float v2 = accs[q].z * dv;
            float v3 = accs[q].w * dv;
            g_hs[o +  0] = v0;  g_agg[o +  0] = v0;
            g_hs[o + 16] = v1;  g_agg[o + 16] = v1;
            g_hs[o + 32] = v2;  g_agg[o + 32] = v2;
            g_hs[o + 48] = v3;  g_agg[o + 48] = v3;
        }
    }
}

// ---------------- edge scatter: agg[dst] += hs[src] ----------------

__global__ void k_scatter(const int* __restrict__ ei, int E) {
    int tid = blockIdx.x * blockDim.x + threadIdx.x;
    int e = tid >> 4;
    if (e >= E) return;
    int lane = tid & 15;
    int src = ei[e];
    int dst = ei[E + e];
    float4 v = ((const float4*)(g_hs + (size_t)src * D))[lane];
    float* p = g_agg + (size_t)dst * D + lane * 4;
    unsigned long long gp;
    asm volatile("cvta.to.global.u64 %0, %1;" : "=l"(gp) : "l"(p));
    asm volatile("red.global.add.v4.f32 [%0], {%1,%2,%3,%4};"
                 :: "l"(gp), "f"(v.x), "f"(v.y), "f"(v.z), "f"(v.w)
                 : "memory");
}

// ---------------- final epilogue: out = prelu(agg*dinv + b, a) ----------------

__global__ void k_epi(const float* __restrict__ b, const float* __restrict__ a,
                      float* __restrict__ out, int n) {
    int tid = blockIdx.x * blockDim.x + threadIdx.x;
    int node = tid >> 4;
    if (node >= n) return;
    int q = tid & 15;
    float dinv = g_dinv[node];
    float4 v  = ((const float4*)g_agg)[(size_t)node * 16 + q];
    float4 bb = ((const float4*)b)[q];
    float4 aa = ((const float4*)a)[q];
    v.x = v.x * dinv + bb.x; v.x = (v.x >= 0.f) ? v.x : aa.x * v.x;
    v.y = v.y * dinv + bb.y; v.y = (v.y >= 0.f) ? v.y : aa.y * v.y;
    v.z = v.z * dinv + bb.z; v.z = (v.z >= 0.f) ? v.z : aa.z * v.z;
    v.w = v.w * dinv + bb.w; v.w = (v.w >= 0.f) ? v.w : aa.w * v.w;
    ((float4*)out)[(size_t)node * 16 + q] = v;
}

// ---------------- launch ----------------

extern "C" void kernel_launch(void* const* d_in, const int* in_sizes, int n_in,
                              void* d_out, int out_size) {
    const float* x  = (const float*)d_in[0];
    const int*   ei = (const int*)d_in[1];     // int32 (JAX x64 disabled)
    const float* W1 = (const float*)d_in[2];
    const float* b1 = (const float*)d_in[3];
    const float* a1 = (const float*)d_in[4];
    const float* W2 = (const float*)d_in[5];
    const float* b2 = (const float*)d_in[6];
    const float* a2 = (const float*)d_in[7];
    float* out = (float*)d_out;

    int n = in_sizes[0] / D;
    int E = in_sizes[1] / 2;

    int nb_n   = (n + 255) / 256;
    int nb_e   = (E + 255) / 256;
    int nb_gm  = (n + 63) / 64;
    int nb_sc  = (int)(((long long)E * 16 + 255) / 256);
    int nb_epi = (int)(((long long)n * 16 + 255) / 256);

    k_init_deg<<<nb_n, 256>>>(n);
    k_count   <<<nb_e, 256>>>(ei, E);
    k_dinv    <<<nb_n, 256>>>(n);

    // layer 1
    k_gemm   <<<nb_gm, 512>>>(x, W1, b1, a1, n, 0);
    k_scatter<<<nb_sc, 256>>>(ei, E);

    // layer 2 (layer-1 epilogue fused into GEMM staging)
    k_gemm   <<<nb_gm, 512>>>(x, W2, b1, a1, n, 1);
    k_scatter<<<nb_sc, 256>>>(ei, E);
    k_epi    <<<nb_epi, 256>>>(b2, a2, out, n);
}